// round 3
// baseline (speedup 1.0000x reference)
#include <cuda_runtime.h>
#include <math.h>
#include <stdint.h>

#define N_TOK 1024
#define H 2048
#define E 64
#define I_DIM 512
#define TOPK 8
#define CAP 256          // max tokens per expert (counts ~128 +- 11; 12-sigma margin)
#define KC 16            // K-chunk per smem stage

// ---------------- scratch (static device globals; zero-initialized) ----------------
__device__ float d_logits[N_TOK * E];
__device__ int   d_topi[N_TOK * TOPK];
__device__ float d_topw[N_TOK * TOPK];
__device__ float d_shg[N_TOK];
__device__ int   d_lists[E * CAP];
__device__ float d_lw[E * CAP];
__device__ int   d_counts[E];
__device__ float d_inter[(size_t)E * CAP * I_DIM];     // 32 MB, padded rows stay 0
__device__ float d_intersh[(size_t)N_TOK * I_DIM];     // 2 MB

// ---------------- helpers ----------------
__device__ __forceinline__ unsigned f2tf(float f) {
    unsigned u;
    asm("cvt.rna.tf32.f32 %0, %1;" : "=r"(u) : "f"(f));
    return u;
}
__device__ __forceinline__ void mma8(float* c, const unsigned* a, const unsigned* b) {
    asm volatile(
        "mma.sync.aligned.m16n8k8.row.col.f32.tf32.tf32.f32 "
        "{%0,%1,%2,%3},{%4,%5,%6,%7},{%8,%9},{%0,%1,%2,%3};"
        : "+f"(c[0]), "+f"(c[1]), "+f"(c[2]), "+f"(c[3])
        : "r"(a[0]), "r"(a[1]), "r"(a[2]), "r"(a[3]), "r"(b[0]), "r"(b[1]));
}
__device__ __forceinline__ void cpa16(void* s, const void* g) {
    unsigned sa = (unsigned)__cvta_generic_to_shared(s);
    asm volatile("cp.async.cg.shared.global [%0], [%1], 16;" :: "r"(sa), "l"(g));
}
__device__ __forceinline__ void cp_commit() { asm volatile("cp.async.commit_group;"); }
__device__ __forceinline__ void ldsm4(unsigned& r0, unsigned& r1, unsigned& r2, unsigned& r3,
                                      const void* p) {
    unsigned a = (unsigned)__cvta_generic_to_shared(p);
    asm volatile("ldmatrix.sync.aligned.m8n8.x4.shared.b16 {%0,%1,%2,%3},[%4];"
                 : "=r"(r0), "=r"(r1), "=r"(r2), "=r"(r3) : "r"(a));
}
__device__ __forceinline__ void cvt4_inplace(float* p) {
    float4 v = *(float4*)p;
    unsigned* u = (unsigned*)p;
    u[0] = f2tf(v.x); u[1] = f2tf(v.y); u[2] = f2tf(v.z); u[3] = f2tf(v.w);
}

// ---------------- K0: routing logits GEMM, full fp32 FFMA ----------------
__global__ __launch_bounds__(256) void k_logits(const float* __restrict__ x,
                                                const float* __restrict__ gw) {
    const int m0 = blockIdx.x * 64;
    __shared__ float As[64][17];
    __shared__ float Bs[64][17];
    const int tid = threadIdx.x;
    const int tr = tid >> 4, tc = tid & 15;
    float acc[4][4] = {};
    const int r = tid >> 2, s4 = (tid & 3) * 4;
    for (int k0 = 0; k0 < H; k0 += 16) {
        float4 av = *(const float4*)(x + (size_t)(m0 + r) * H + k0 + s4);
        float4 bv = *(const float4*)(gw + (size_t)r * H + k0 + s4);
        __syncthreads();
        As[r][s4 + 0] = av.x; As[r][s4 + 1] = av.y; As[r][s4 + 2] = av.z; As[r][s4 + 3] = av.w;
        Bs[r][s4 + 0] = bv.x; Bs[r][s4 + 1] = bv.y; Bs[r][s4 + 2] = bv.z; Bs[r][s4 + 3] = bv.w;
        __syncthreads();
#pragma unroll
        for (int kk = 0; kk < 16; kk++) {
            float a[4], b[4];
#pragma unroll
            for (int i = 0; i < 4; i++) { a[i] = As[tr * 4 + i][kk]; b[i] = Bs[tc * 4 + i][kk]; }
#pragma unroll
            for (int i = 0; i < 4; i++)
#pragma unroll
                for (int j = 0; j < 4; j++) acc[i][j] += a[i] * b[j];
        }
    }
#pragma unroll
    for (int i = 0; i < 4; i++)
#pragma unroll
        for (int j = 0; j < 4; j++)
            d_logits[(size_t)(m0 + tr * 4 + i) * E + tc * 4 + j] = acc[i][j];
}

// ---------------- K1: per-token top-8 (warp argmax) + softmax + shared-gate sigmoid ----
__global__ __launch_bounds__(64) void k_topk(const float* __restrict__ x,
                                             const float* __restrict__ sh1) {
    const int n = blockIdx.x;
    const int t = threadIdx.x;
    const int lane = t & 31, w = t >> 5;
    __shared__ float red[2];
    float p = 0.f;
    const float* xr = x + (size_t)n * H;
    for (int i = t; i < H; i += 64) p += xr[i] * sh1[i];
#pragma unroll
    for (int off = 16; off; off >>= 1) p += __shfl_xor_sync(0xffffffffu, p, off);
    if (lane == 0) red[w] = p;
    __syncthreads();
    if (t == 0) {
        float s = red[0] + red[1];
        d_shg[n] = 1.f / (1.f + expf(-s));
    }
    if (w == 0) {
        float a = d_logits[(size_t)n * E + lane];
        float b = d_logits[(size_t)n * E + 32 + lane];
        float vv[TOPK]; int ii[TOPK];
#pragma unroll
        for (int k = 0; k < TOPK; k++) {
            float m; int mi;
            if (a >= b) { m = a; mi = lane; } else { m = b; mi = lane + 32; }
#pragma unroll
            for (int off = 16; off; off >>= 1) {
                float om = __shfl_xor_sync(0xffffffffu, m, off);
                int   oi = __shfl_xor_sync(0xffffffffu, mi, off);
                if (om > m || (om == m && oi < mi)) { m = om; mi = oi; }
            }
            vv[k] = m; ii[k] = mi;
            if (lane == (mi & 31)) { if (mi < 32) a = -INFINITY; else b = -INFINITY; }
        }
        if (lane == 0) {
            float mx = vv[0], se = 0.f, ev[TOPK];
#pragma unroll
            for (int k = 0; k < TOPK; k++) { ev[k] = expf(vv[k] - mx); se += ev[k]; }
#pragma unroll
            for (int k = 0; k < TOPK; k++) {
                d_topi[n * TOPK + k] = ii[k];
                d_topw[n * TOPK + k] = ev[k] / se;
            }
        }
    }
}

// ---------------- K2: deterministic per-expert compaction ----------------
__global__ __launch_bounds__(256) void k_build() {
    const int e = blockIdx.x, t = threadIdx.x;
    __shared__ int wsum[8];
    __shared__ int base_s;
    if (t == 0) base_s = 0;
    __syncthreads();
    for (int c0 = 0; c0 < N_TOK * TOPK; c0 += 256) {
        int idx = c0 + t;
        int pred = (d_topi[idx] == e) ? 1 : 0;
        unsigned bal = __ballot_sync(0xffffffffu, pred);
        if ((t & 31) == 0) wsum[t >> 5] = __popc(bal);
        __syncthreads();
        int off = 0;
#pragma unroll
        for (int w = 0; w < 8; w++) if (w < (t >> 5)) off += wsum[w];
        int tot = 0;
#pragma unroll
        for (int w = 0; w < 8; w++) tot += wsum[w];
        int pos = base_s + off + __popc(bal & ((1u << (t & 31)) - 1u));
        if (pred && pos < CAP) {
            d_lists[e * CAP + pos] = idx >> 3;
            d_lw[e * CAP + pos] = d_topw[idx];
        }
        __syncthreads();
        if (t == 0) base_s += tot;
        __syncthreads();
    }
    if (t == 0) d_counts[e] = (base_s > CAP) ? CAP : base_s;
}

// ---------------- K3: fused gate/up tf32 GEMM + silu epilogue ----------------
// shared_mode=0: expert = blockIdx.x (grid 64 x 2 x 8)
// shared_mode=1: shared expert      (grid 1 x 8 x 8)
__global__ __launch_bounds__(256, 2) void k_gated(const float* __restrict__ x,
                                                  const float* __restrict__ gu_w,
                                                  const float* __restrict__ shg_w,
                                                  const float* __restrict__ shu_w,
                                                  int shared_mode) {
    const bool moe = !shared_mode;
    const int e = moe ? blockIdx.x : E;
    const int m0 = blockIdx.y * 128;
    const int j0 = blockIdx.z * 64;
    const int cnt = moe ? d_counts[e] : N_TOK;
    if (m0 >= cnt) return;
    const float* Bg = moe ? gu_w + ((size_t)e * 2 * I_DIM + j0) * H : shg_w + (size_t)j0 * H;
    const float* Bu = moe ? gu_w + ((size_t)e * 2 * I_DIM + I_DIM + j0) * H : shu_w + (size_t)j0 * H;

    __shared__ __align__(16) float As[2][128][KC + 4];
    __shared__ __align__(16) float Bs[2][2][64][KC + 4];
    __shared__ int toks[128];
    __shared__ float wr[128];

    const int tid = threadIdx.x;
    for (int r = tid; r < 128; r += 256) {
        int slot = m0 + r;
        if (moe) {
            bool v = slot < cnt;
            toks[r] = v ? d_lists[e * CAP + slot] : 0;
            wr[r]   = v ? d_lw[e * CAP + slot] : 0.f;
        } else {
            toks[r] = slot;
            wr[r] = 1.f;
        }
    }
    __syncthreads();

    auto load_stage = [&](int s) {
        int buf = s & 1, k0 = s * KC;
        for (int c = tid; c < 512; c += 256) {
            int r = c >> 2, seg = c & 3;
            cpa16(&As[buf][r][seg * 4], x + (size_t)toks[r] * H + k0 + seg * 4);
        }
        for (int c = tid; c < 512; c += 256) {
            int hh = c >> 8, rr = (c >> 2) & 63, seg = c & 3;
            const float* src = (hh ? Bu : Bg) + (size_t)rr * H + k0 + seg * 4;
            cpa16(&Bs[buf][hh][rr][seg * 4], src);
        }
        cp_commit();
    };
    auto cvt_stage = [&](int buf) {
        for (int c = tid; c < 512; c += 256)
            cvt4_inplace(&As[buf][c >> 2][(c & 3) * 4]);
        for (int c = tid; c < 512; c += 256)
            cvt4_inplace(&Bs[buf][c >> 8][(c >> 2) & 63][(c & 3) * 4]);
    };

    float accG[2][4][4] = {}, accU[2][4][4] = {};
    const int warp = tid >> 5, lane = tid & 31;
    const int wm = warp & 3, wn = warp >> 2;
    const int g = lane >> 2, tg = lane & 3;
    const int lrow = lane & 15;
    const int ksh  = (lane >> 2) & 4;
    const int arow = wm * 32 + lrow;
    const int brow = wn * 32 + lrow;
    const int NS = H / KC;

    load_stage(0);
    for (int s = 0; s < NS; s++) {
        if (s + 1 < NS) { load_stage(s + 1); asm volatile("cp.async.wait_group 1;"); }
        else            { asm volatile("cp.async.wait_group 0;"); }
        __syncthreads();
        const int buf = s & 1;
        cvt_stage(buf);
        __syncthreads();
#pragma unroll
        for (int k8 = 0; k8 < KC / 8; k8++) {
            const int kc = k8 * 8 + ksh;
            unsigned A0[4], A1[4];
            ldsm4(A0[0], A0[1], A0[2], A0[3], &As[buf][arow][kc]);
            ldsm4(A1[0], A1[1], A1[2], A1[3], &As[buf][arow + 16][kc]);
            unsigned Gf[4][2], Uf[4][2];
            ldsm4(Gf[0][0], Gf[1][0], Gf[0][1], Gf[1][1], &Bs[buf][0][brow][kc]);
            ldsm4(Gf[2][0], Gf[3][0], Gf[2][1], Gf[3][1], &Bs[buf][0][brow + 16][kc]);
            ldsm4(Uf[0][0], Uf[1][0], Uf[0][1], Uf[1][1], &Bs[buf][1][brow][kc]);
            ldsm4(Uf[2][0], Uf[3][0], Uf[2][1], Uf[3][1], &Bs[buf][1][brow + 16][kc]);
#pragma unroll
            for (int ni = 0; ni < 4; ni++) {
                mma8(accG[0][ni], A0, Gf[ni]);
                mma8(accG[1][ni], A1, Gf[ni]);
                mma8(accU[0][ni], A0, Uf[ni]);
                mma8(accU[1][ni], A1, Uf[ni]);
            }
        }
        __syncthreads();
    }

    // epilogue: inter = silu(gate) * up * route_weight
#pragma unroll
    for (int mi = 0; mi < 2; mi++)
#pragma unroll
        for (int ni = 0; ni < 4; ni++) {
            int rb = wm * 32 + mi * 16, cb = wn * 32 + ni * 8;
#pragma unroll
            for (int hh = 0; hh < 2; hh++) {
                int r = rb + g + hh * 8;
                int slot = m0 + r;
                if (slot < cnt) {
                    float w = wr[r];
                    int col = j0 + cb + 2 * tg;
                    float g0 = accG[mi][ni][hh * 2 + 0], g1 = accG[mi][ni][hh * 2 + 1];
                    float u0 = accU[mi][ni][hh * 2 + 0], u1 = accU[mi][ni][hh * 2 + 1];
                    float v0 = (g0 / (1.f + __expf(-g0))) * u0 * w;
                    float v1 = (g1 / (1.f + __expf(-g1))) * u1 * w;
                    float* dst = moe ? d_inter + ((size_t)e * CAP + slot) * I_DIM
                                     : d_intersh + (size_t)slot * I_DIM;
                    dst[col] = v0;
                    dst[col + 1] = v1;
                }
            }
        }
}

// ---------------- K4: down-projection tf32 GEMM ----------------
template <bool MOE>
__global__ __launch_bounds__(256, 2) void k_down(const float* __restrict__ Bsrc,
                                                 float* __restrict__ out) {
    const int e = MOE ? blockIdx.x : 0;
    const int m0 = blockIdx.y * 128, h0 = blockIdx.z * 64;
    const int cnt = MOE ? d_counts[e] : N_TOK;
    if (m0 >= cnt) return;
    const float* A = MOE ? d_inter + (size_t)e * CAP * I_DIM : d_intersh;
    const float* B = MOE ? Bsrc + ((size_t)e * H + h0) * I_DIM : Bsrc + (size_t)h0 * I_DIM;

    __shared__ __align__(16) float As[2][128][KC + 4];
    __shared__ __align__(16) float Bs2[2][64][KC + 4];
    __shared__ int toks[128];
    __shared__ float scl[128];

    const int tid = threadIdx.x;
    for (int r = tid; r < 128; r += 256) {
        int slot = m0 + r;
        if (MOE) toks[r] = (slot < cnt) ? d_lists[e * CAP + slot] : 0;
        else     scl[r] = d_shg[slot];
    }
    __syncthreads();

    auto load_stage = [&](int s) {
        int buf = s & 1, k0 = s * KC;
        for (int c = tid; c < 512; c += 256) {
            int r = c >> 2, seg = c & 3;
            cpa16(&As[buf][r][seg * 4], A + (size_t)(m0 + r) * I_DIM + k0 + seg * 4);
        }
        {
            int c = tid;
            int rr = c >> 2, seg = c & 3;
            cpa16(&Bs2[buf][rr][seg * 4], B + (size_t)rr * I_DIM + k0 + seg * 4);
        }
        cp_commit();
    };
    auto cvt_stage = [&](int buf) {
        for (int c = tid; c < 512; c += 256)
            cvt4_inplace(&As[buf][c >> 2][(c & 3) * 4]);
        {
            int c = tid;
            cvt4_inplace(&Bs2[buf][c >> 2][(c & 3) * 4]);
        }
    };

    float acc[2][4][4] = {};
    const int warp = tid >> 5, lane = tid & 31;
    const int wm = warp & 3, wn = warp >> 2;
    const int g = lane >> 2, tg = lane & 3;
    const int lrow = lane & 15;
    const int ksh  = (lane >> 2) & 4;
    const int arow = wm * 32 + lrow;
    const int brow = wn * 32 + lrow;
    const int NS = I_DIM / KC;

    load_stage(0);
    for (int s = 0; s < NS; s++) {
        if (s + 1 < NS) { load_stage(s + 1); asm volatile("cp.async.wait_group 1;"); }
        else            { asm volatile("cp.async.wait_group 0;"); }
        __syncthreads();
        const int buf = s & 1;
        cvt_stage(buf);
        __syncthreads();
#pragma unroll
        for (int k8 = 0; k8 < KC / 8; k8++) {
            const int kc = k8 * 8 + ksh;
            unsigned A0[4], A1[4];
            ldsm4(A0[0], A0[1], A0[2], A0[3], &As[buf][arow][kc]);
            ldsm4(A1[0], A1[1], A1[2], A1[3], &As[buf][arow + 16][kc]);
            unsigned Bf[4][2];
            ldsm4(Bf[0][0], Bf[1][0], Bf[0][1], Bf[1][1], &Bs2[buf][brow][kc]);
            ldsm4(Bf[2][0], Bf[3][0], Bf[2][1], Bf[3][1], &Bs2[buf][brow + 16][kc]);
#pragma unroll
            for (int ni = 0; ni < 4; ni++) {
                mma8(acc[0][ni], A0, Bf[ni]);
                mma8(acc[1][ni], A1, Bf[ni]);
            }
        }
        __syncthreads();
    }

#pragma unroll
    for (int mi = 0; mi < 2; mi++)
#pragma unroll
        for (int ni = 0; ni < 4; ni++) {
            int rb = wm * 32 + mi * 16, cb = wn * 32 + ni * 8;
#pragma unroll
            for (int hh = 0; hh < 2; hh++) {
                int r = rb + g + hh * 8;
                int slot = m0 + r;
                int col = h0 + cb + 2 * tg;
                float v0 = acc[mi][ni][hh * 2 + 0];
                float v1 = acc[mi][ni][hh * 2 + 1];
                if (MOE) {
                    if (slot < cnt) {
                        int tk = toks[r];
                        atomicAdd(out + (size_t)tk * H + col, v0);
                        atomicAdd(out + (size_t)tk * H + col + 1, v1);
                    }
                } else {
                    float sc = scl[r];
                    out[(size_t)slot * H + col] = sc * v0;
                    out[(size_t)slot * H + col + 1] = sc * v1;
                }
            }
        }
}

// ---------------- launcher ----------------
extern "C" void kernel_launch(void* const* d_in, const int* in_sizes, int n_in,
                              void* d_out, int out_size) {
    (void)in_sizes; (void)n_in; (void)out_size;
    const float* x      = (const float*)d_in[0];
    const float* gate_w = (const float*)d_in[1];
    const float* gu_w   = (const float*)d_in[2];
    const float* dp_w   = (const float*)d_in[3];
    const float* shg_w  = (const float*)d_in[4];
    const float* shu_w  = (const float*)d_in[5];
    const float* shd_w  = (const float*)d_in[6];
    const float* sh1    = (const float*)d_in[7];
    float* out = (float*)d_out;

    k_logits<<<16, 256>>>(x, gate_w);
    k_topk<<<N_TOK, 64>>>(x, sh1);
    k_build<<<E, 256>>>();
    k_gated<<<dim3(E, 2, 8), 256>>>(x, gu_w, shg_w, shu_w, 0);   // MoE experts
    k_gated<<<dim3(1, 8, 8), 256>>>(x, gu_w, shg_w, shu_w, 1);   // shared expert
    k_down<false><<<dim3(1, 8, 32), 256>>>(shd_w, out);          // init out with shared expert
    k_down<true><<<dim3(E, 2, 32), 256>>>(dp_w, out);            // atomic-accumulate experts
}

// round 7
// speedup vs baseline: 1.2456x; 1.2456x over previous
#include <cuda_runtime.h>
#include <math.h>
#include <stdint.h>

#define N_TOK 1024
#define H 2048
#define E 64
#define I_DIM 512
#define TOPK 8
#define CAP 256          // max tokens per expert (counts ~128 +- 11)
#define KC 16            // K floats per stage

// ---------------- scratch (static device globals; zero-initialized) ----------------
__device__ float d_logits[N_TOK * E];
__device__ int   d_topi[N_TOK * TOPK];
__device__ float d_topw[N_TOK * TOPK];
__device__ float d_shg[N_TOK];
__device__ int   d_lists[E * CAP];
__device__ float d_lw[E * CAP];
__device__ int   d_counts[E];
__device__ float d_inter[(size_t)E * CAP * I_DIM];     // stored as tf32 bit patterns
__device__ float d_intersh[(size_t)N_TOK * I_DIM];     // stored as tf32 bit patterns

// ---------------- helpers ----------------
__device__ __forceinline__ unsigned f2tf(float f) {
    unsigned u;
    asm("cvt.rna.tf32.f32 %0, %1;" : "=r"(u) : "f"(f));
    return u;
}
__device__ __forceinline__ void mma8(float* c, const unsigned* a, const unsigned* b) {
    asm volatile(
        "mma.sync.aligned.m16n8k8.row.col.f32.tf32.tf32.f32 "
        "{%0,%1,%2,%3},{%4,%5,%6,%7},{%8,%9},{%0,%1,%2,%3};"
        : "+f"(c[0]), "+f"(c[1]), "+f"(c[2]), "+f"(c[3])
        : "r"(a[0]), "r"(a[1]), "r"(a[2]), "r"(a[3]), "r"(b[0]), "r"(b[1]));
}
__device__ __forceinline__ void ldsm4(unsigned& r0, unsigned& r1, unsigned& r2, unsigned& r3,
                                      const void* p) {
    unsigned a = (unsigned)__cvta_generic_to_shared(p);
    asm volatile("ldmatrix.sync.aligned.m8n8.x4.shared.b16 {%0,%1,%2,%3},[%4];"
                 : "=r"(r0), "=r"(r1), "=r"(r2), "=r"(r3) : "r"(a));
}
__device__ __forceinline__ uint4 cvt4(float4 v) {
    uint4 u;
    u.x = f2tf(v.x); u.y = f2tf(v.y); u.z = f2tf(v.z); u.w = f2tf(v.w);
    return u;
}
__device__ __forceinline__ void red2(float* p, float v0, float v1) {
    asm volatile("red.global.add.v2.f32 [%0], {%1,%2};" :: "l"(p), "f"(v0), "f"(v1) : "memory");
}

// ---------------- K0: routing logits GEMM (fp32 FFMA) ----------------
__global__ __launch_bounds__(256) void k_logits(const float* __restrict__ x,
                                                const float* __restrict__ gw) {
    const int m0 = blockIdx.x * 64;
    __shared__ float As[64][17];
    __shared__ float Bs[64][17];
    const int tid = threadIdx.x;
    const int tr = tid >> 4, tc = tid & 15;
    float acc[4][4] = {};
    const int r = tid >> 2, s4 = (tid & 3) * 4;
    for (int k0 = 0; k0 < H; k0 += 16) {
        float4 av = *(const float4*)(x + (size_t)(m0 + r) * H + k0 + s4);
        float4 bv = *(const float4*)(gw + (size_t)r * H + k0 + s4);
        __syncthreads();
        As[r][s4+0]=av.x; As[r][s4+1]=av.y; As[r][s4+2]=av.z; As[r][s4+3]=av.w;
        Bs[r][s4+0]=bv.x; Bs[r][s4+1]=bv.y; Bs[r][s4+2]=bv.z; Bs[r][s4+3]=bv.w;
        __syncthreads();
#pragma unroll
        for (int kk = 0; kk < 16; kk++) {
            float a[4], b[4];
#pragma unroll
            for (int i = 0; i < 4; i++) { a[i] = As[tr*4+i][kk]; b[i] = Bs[tc*4+i][kk]; }
#pragma unroll
            for (int i = 0; i < 4; i++)
#pragma unroll
                for (int j = 0; j < 4; j++) acc[i][j] += a[i] * b[j];
        }
    }
#pragma unroll
    for (int i = 0; i < 4; i++)
#pragma unroll
        for (int j = 0; j < 4; j++)
            d_logits[(size_t)(m0 + tr*4 + i) * E + tc*4 + j] = acc[i][j];
}

// ---------------- K1: top-8 (warp argmax) + softmax + shared-gate sigmoid ----------
__global__ __launch_bounds__(64) void k_topk(const float* __restrict__ x,
                                             const float* __restrict__ sh1) {
    const int n = blockIdx.x;
    const int t = threadIdx.x;
    const int lane = t & 31, w = t >> 5;
    __shared__ float red[2];
    float p = 0.f;
    const float* xr = x + (size_t)n * H;
    for (int i = t; i < H; i += 64) p += xr[i] * sh1[i];
#pragma unroll
    for (int off = 16; off; off >>= 1) p += __shfl_xor_sync(0xffffffffu, p, off);
    if (lane == 0) red[w] = p;
    __syncthreads();
    if (t == 0) {
        float s = red[0] + red[1];
        d_shg[n] = 1.f / (1.f + expf(-s));
    }
    if (w == 0) {
        float a = d_logits[(size_t)n * E + lane];
        float b = d_logits[(size_t)n * E + 32 + lane];
        float vv[TOPK]; int ii[TOPK];
#pragma unroll
        for (int k = 0; k < TOPK; k++) {
            float m; int mi;
            if (a >= b) { m = a; mi = lane; } else { m = b; mi = lane + 32; }
#pragma unroll
            for (int off = 16; off; off >>= 1) {
                float om = __shfl_xor_sync(0xffffffffu, m, off);
                int   oi = __shfl_xor_sync(0xffffffffu, mi, off);
                if (om > m || (om == m && oi < mi)) { m = om; mi = oi; }
            }
            vv[k] = m; ii[k] = mi;
            if (lane == (mi & 31)) { if (mi < 32) a = -INFINITY; else b = -INFINITY; }
        }
        if (lane == 0) {
            float mx = vv[0], se = 0.f, ev[TOPK];
#pragma unroll
            for (int k = 0; k < TOPK; k++) { ev[k] = expf(vv[k] - mx); se += ev[k]; }
#pragma unroll
            for (int k = 0; k < TOPK; k++) {
                d_topi[n * TOPK + k] = ii[k];
                d_topw[n * TOPK + k] = ev[k] / se;
            }
        }
    }
}

// ---------------- K2: deterministic per-expert compaction ----------------
__global__ __launch_bounds__(256) void k_build() {
    const int e = blockIdx.x, t = threadIdx.x;
    __shared__ int wsum[8];
    __shared__ int base_s;
    if (t == 0) base_s = 0;
    __syncthreads();
    for (int c0 = 0; c0 < N_TOK * TOPK; c0 += 256) {
        int idx = c0 + t;
        int pred = (d_topi[idx] == e) ? 1 : 0;
        unsigned bal = __ballot_sync(0xffffffffu, pred);
        if ((t & 31) == 0) wsum[t >> 5] = __popc(bal);
        __syncthreads();
        int off = 0;
#pragma unroll
        for (int w = 0; w < 8; w++) if (w < (t >> 5)) off += wsum[w];
        int tot = 0;
#pragma unroll
        for (int w = 0; w < 8; w++) tot += wsum[w];
        int pos = base_s + off + __popc(bal & ((1u << (t & 31)) - 1u));
        if (pred && pos < CAP) {
            d_lists[e * CAP + pos] = idx >> 3;
            d_lw[e * CAP + pos] = d_topw[idx];
        }
        __syncthreads();
        if (t == 0) base_s += tot;
        __syncthreads();
    }
    if (t == 0) d_counts[e] = (base_s > CAP) ? CAP : base_s;
}

// ---------------- K3: fused gate/up tf32 GEMM (LDG->cvt->STS staging + ldmatrix) ----
// moe: grid (E, 2, 8); shared: grid (1, 8, 8). Tile M=128, N=64(+64 up), K full.
__global__ __launch_bounds__(256, 2) void k_gated(const float* __restrict__ x,
                                                  const float* __restrict__ gu_w,
                                                  const float* __restrict__ shg_w,
                                                  const float* __restrict__ shu_w,
                                                  int shared_mode) {
    const bool moe = !shared_mode;
    const int e = blockIdx.x;
    const int m0 = blockIdx.y * 128;
    const int j0 = blockIdx.z * 64;
    const int cnt = moe ? d_counts[e] : N_TOK;
    if (m0 >= cnt) return;
    const float* Bg = moe ? gu_w + ((size_t)e * 2 * I_DIM + j0) * H : shg_w + (size_t)j0 * H;
    const float* Bu = moe ? gu_w + ((size_t)e * 2 * I_DIM + I_DIM + j0) * H : shu_w + (size_t)j0 * H;

    __shared__ __align__(16) float As[2][128][KC + 4];
    __shared__ __align__(16) float Bs[2][2][64][KC + 4];
    __shared__ int toks[128];
    __shared__ float wr[128];

    const int tid = threadIdx.x;
    for (int r = tid; r < 128; r += 256) {
        int slot = m0 + r;
        if (moe) {
            bool v = slot < cnt;
            toks[r] = v ? d_lists[e * CAP + slot] : 0;
            wr[r]   = v ? d_lw[e * CAP + slot] : 0.f;
        } else { toks[r] = slot; wr[r] = 1.f; }
    }
    __syncthreads();

    // fixed per-thread staging assignment: 2 A chunks + 2 B chunks of 16B
    const float* aptr[2];
    const float* bptr[2];
    int ar[2], aseg[2], bh[2], brr[2], bseg[2];
#pragma unroll
    for (int i = 0; i < 2; i++) {
        int c = tid + i * 256;
        ar[i] = c >> 2; aseg[i] = c & 3;
        aptr[i] = x + (size_t)toks[ar[i]] * H + aseg[i] * 4;
    }
#pragma unroll
    for (int i = 0; i < 2; i++) {
        int c = tid + i * 256;
        bh[i] = c >> 8; brr[i] = (c >> 2) & 63; bseg[i] = c & 3;
        bptr[i] = (bh[i] ? Bu : Bg) + (size_t)brr[i] * H + bseg[i] * 4;
    }

    float4 pa[2], pb[2];
    auto ldg_stage = [&](int s) {
        int k0 = s * KC;
#pragma unroll
        for (int i = 0; i < 2; i++) pa[i] = *(const float4*)(aptr[i] + k0);
#pragma unroll
        for (int i = 0; i < 2; i++) pb[i] = *(const float4*)(bptr[i] + k0);
    };
    auto sts_stage = [&](int buf) {
#pragma unroll
        for (int i = 0; i < 2; i++)
            *(uint4*)&As[buf][ar[i]][aseg[i] * 4] = cvt4(pa[i]);
#pragma unroll
        for (int i = 0; i < 2; i++)
            *(uint4*)&Bs[buf][bh[i]][brr[i]][bseg[i] * 4] = cvt4(pb[i]);
    };

    float accG[2][4][4] = {}, accU[2][4][4] = {};
    const int warp = tid >> 5, lane = tid & 31;
    const int wm = warp & 3, wn = warp >> 2;
    const int g = lane >> 2, tg = lane & 3;
    const int lrow = lane & 15;
    const int ksh  = (lane >> 2) & 4;
    const int arow = wm * 32 + lrow;
    const int brow = wn * 32 + lrow;
    const int NS = H / KC;   // 128

    ldg_stage(0);
    sts_stage(0);
    ldg_stage(1);
    __syncthreads();
    for (int s = 0; s < NS; s++) {
        const int buf = s & 1;
        if (s + 1 < NS) sts_stage(1 - buf);   // stores stage s+1 from regs
        if (s + 2 < NS) ldg_stage(s + 2);     // refill regs; latency hidden by MMAs
#pragma unroll
        for (int k8 = 0; k8 < KC / 8; k8++) {
            const int kc = k8 * 8 + ksh;
            unsigned A0[4], A1[4];
            ldsm4(A0[0], A0[1], A0[2], A0[3], &As[buf][arow][kc]);
            ldsm4(A1[0], A1[1], A1[2], A1[3], &As[buf][arow + 16][kc]);
            unsigned Gf[4][2], Uf[4][2];
            ldsm4(Gf[0][0], Gf[1][0], Gf[0][1], Gf[1][1], &Bs[buf][0][brow][kc]);
            ldsm4(Gf[2][0], Gf[3][0], Gf[2][1], Gf[3][1], &Bs[buf][0][brow + 16][kc]);
            ldsm4(Uf[0][0], Uf[1][0], Uf[0][1], Uf[1][1], &Bs[buf][1][brow][kc]);
            ldsm4(Uf[2][0], Uf[3][0], Uf[2][1], Uf[3][1], &Bs[buf][1][brow + 16][kc]);
#pragma unroll
            for (int ni = 0; ni < 4; ni++) {
                mma8(accG[0][ni], A0, Gf[ni]);
                mma8(accG[1][ni], A1, Gf[ni]);
                mma8(accU[0][ni], A0, Uf[ni]);
                mma8(accU[1][ni], A1, Uf[ni]);
            }
        }
        __syncthreads();
    }

    // epilogue: inter = tf32( silu(gate)*up*route_w )
#pragma unroll
    for (int mi = 0; mi < 2; mi++)
#pragma unroll
        for (int ni = 0; ni < 4; ni++) {
            int rb = wm * 32 + mi * 16, cb = wn * 32 + ni * 8;
#pragma unroll
            for (int hh = 0; hh < 2; hh++) {
                int r = rb + g + hh * 8;
                int slot = m0 + r;
                if (slot < cnt) {
                    float w = wr[r];
                    int col = j0 + cb + 2 * tg;
                    float g0 = accG[mi][ni][hh*2+0], g1 = accG[mi][ni][hh*2+1];
                    float u0 = accU[mi][ni][hh*2+0], u1 = accU[mi][ni][hh*2+1];
                    float v0 = (g0 / (1.f + __expf(-g0))) * u0 * w;
                    float v1 = (g1 / (1.f + __expf(-g1))) * u1 * w;
                    float* dst = moe ? d_inter + ((size_t)e * CAP + slot) * I_DIM
                                     : d_intersh + (size_t)slot * I_DIM;
                    dst[col]     = __uint_as_float(f2tf(v0));
                    dst[col + 1] = __uint_as_float(f2tf(v1));
                }
            }
        }
}

// ---------------- K4: down-projection tf32 GEMM (A already tf32 in scratch) -------
template <bool MOE>
__global__ __launch_bounds__(256, 2) void k_down(const float* __restrict__ Bsrc,
                                                 float* __restrict__ out) {
    const int e = MOE ? blockIdx.x : 0;
    const int m0 = blockIdx.y * 128, h0 = blockIdx.z * 64;
    const int cnt = MOE ? d_counts[e] : N_TOK;
    if (m0 >= cnt) return;
    const float* A = MOE ? d_inter + (size_t)e * CAP * I_DIM : d_intersh;
    const float* B = MOE ? Bsrc + ((size_t)e * H + h0) * I_DIM : Bsrc + (size_t)h0 * I_DIM;

    __shared__ __align__(16) float As[2][128][KC + 4];
    __shared__ __align__(16) float Bs2[2][64][KC + 4];
    __shared__ int toks[128];
    __shared__ float scl[128];

    const int tid = threadIdx.x;
    for (int r = tid; r < 128; r += 256) {
        int slot = m0 + r;
        if (MOE) toks[r] = (slot < cnt) ? d_lists[e * CAP + slot] : 0;
        else     scl[r] = d_shg[slot];
    }
    __syncthreads();

    // staging: 2 A chunks (raw tf32 bits, no cvt) + 1 B chunk (cvt) per thread
    const float* aptr[2];
    int ar[2], aseg[2];
#pragma unroll
    for (int i = 0; i < 2; i++) {
        int c = tid + i * 256;
        ar[i] = c >> 2; aseg[i] = c & 3;
        aptr[i] = A + (size_t)(m0 + ar[i]) * I_DIM + aseg[i] * 4;
    }
    const int brr = tid >> 2, bseg = tid & 3;
    const float* bptr = B + (size_t)brr * I_DIM + bseg * 4;

    float4 pa[2], pb;
    auto ldg_stage = [&](int s) {
        int k0 = s * KC;
#pragma unroll
        for (int i = 0; i < 2; i++) pa[i] = *(const float4*)(aptr[i] + k0);
        pb = *(const float4*)(bptr + k0);
    };
    auto sts_stage = [&](int buf) {
#pragma unroll
        for (int i = 0; i < 2; i++)
            *(float4*)&As[buf][ar[i]][aseg[i] * 4] = pa[i];     // already tf32 bits
        *(uint4*)&Bs2[buf][brr][bseg * 4] = cvt4(pb);
    };

    float acc[2][4][4] = {};
    const int warp = tid >> 5, lane = tid & 31;
    const int wm = warp & 3, wn = warp >> 2;
    const int g = lane >> 2, tg = lane & 3;
    const int lrow = lane & 15;
    const int ksh  = (lane >> 2) & 4;
    const int arow = wm * 32 + lrow;
    const int brow = wn * 32 + lrow;
    const int NS = I_DIM / KC;   // 32

    ldg_stage(0);
    sts_stage(0);
    ldg_stage(1);
    __syncthreads();
    for (int s = 0; s < NS; s++) {
        const int buf = s & 1;
        if (s + 1 < NS) sts_stage(1 - buf);
        if (s + 2 < NS) ldg_stage(s + 2);
#pragma unroll
        for (int k8 = 0; k8 < KC / 8; k8++) {
            const int kc = k8 * 8 + ksh;
            unsigned A0[4], A1[4];
            ldsm4(A0[0], A0[1], A0[2], A0[3], &As[buf][arow][kc]);
            ldsm4(A1[0], A1[1], A1[2], A1[3], &As[buf][arow + 16][kc]);
            unsigned Bf[4][2];
            ldsm4(Bf[0][0], Bf[1][0], Bf[0][1], Bf[1][1], &Bs2[buf][brow][kc]);
            ldsm4(Bf[2][0], Bf[3][0], Bf[2][1], Bf[3][1], &Bs2[buf][brow + 16][kc]);
#pragma unroll
            for (int ni = 0; ni < 4; ni++) {
                mma8(acc[0][ni], A0, Bf[ni]);
                mma8(acc[1][ni], A1, Bf[ni]);
            }
        }
        __syncthreads();
    }

#pragma unroll
    for (int mi = 0; mi < 2; mi++)
#pragma unroll
        for (int ni = 0; ni < 4; ni++) {
            int rb = wm * 32 + mi * 16, cb = wn * 32 + ni * 8;
#pragma unroll
            for (int hh = 0; hh < 2; hh++) {
                int r = rb + g + hh * 8;
                int slot = m0 + r;
                int col = h0 + cb + 2 * tg;
                float v0 = acc[mi][ni][hh*2+0];
                float v1 = acc[mi][ni][hh*2+1];
                if (MOE) {
                    if (slot < cnt) {
                        int tk = toks[r];
                        red2(out + (size_t)tk * H + col, v0, v1);
                    }
                } else {
                    float sc = scl[r];
                    out[(size_t)slot * H + col]     = sc * v0;
                    out[(size_t)slot * H + col + 1] = sc * v1;
                }
            }
        }
}

// ---------------- launcher ----------------
extern "C" void kernel_launch(void* const* d_in, const int* in_sizes, int n_in,
                              void* d_out, int out_size) {
    (void)in_sizes; (void)n_in; (void)out_size;
    const float* x      = (const float*)d_in[0];
    const float* gate_w = (const float*)d_in[1];
    const float* gu_w   = (const float*)d_in[2];
    const float* dp_w   = (const float*)d_in[3];
    const float* shg_w  = (const float*)d_in[4];
    const float* shu_w  = (const float*)d_in[5];
    const float* shd_w  = (const float*)d_in[6];
    const float* sh1    = (const float*)d_in[7];
    float* out = (float*)d_out;

    k_logits<<<16, 256>>>(x, gate_w);
    k_topk<<<N_TOK, 64>>>(x, sh1);
    k_build<<<E, 256>>>();
    k_gated<<<dim3(E, 2, 8), 256>>>(x, gu_w, shg_w, shu_w, 0);   // MoE experts
    k_gated<<<dim3(1, 8, 8), 256>>>(x, gu_w, shg_w, shu_w, 1);   // shared expert
    k_down<false><<<dim3(1, 8, 32), 256>>>(shd_w, out);          // init out (shared expert)
    k_down<true><<<dim3(E, 2, 32), 256>>>(dp_w, out);            // red.v2-accumulate experts
}

// round 10
// speedup vs baseline: 1.6692x; 1.3401x over previous
#include <cuda_runtime.h>
#include <math.h>
#include <stdint.h>

#define N_TOK 1024
#define H 2048
#define E 64
#define I_DIM 512
#define TOPK 8
#define CAP 256          // max tokens per expert (counts ~128 +- 11)
#define KC 16            // K floats per stage
#define KSPLIT 4

// ---------------- scratch (static device globals; zero-initialized) ----------------
__device__ float d_logits4[KSPLIT][N_TOK * E];
__device__ int   d_topi[N_TOK * TOPK];
__device__ float d_topw[N_TOK * TOPK];
__device__ float d_shg[N_TOK];
__device__ int   d_lists[E * CAP];
__device__ float d_lw[E * CAP];
__device__ int   d_counts[E];
__device__ float d_inter[(size_t)E * CAP * I_DIM];     // tf32 bit patterns
__device__ float d_intersh[(size_t)N_TOK * I_DIM];     // tf32 bit patterns

// ---------------- helpers ----------------
__device__ __forceinline__ unsigned f2tf(float f) {
    unsigned u;
    asm("cvt.rna.tf32.f32 %0, %1;" : "=r"(u) : "f"(f));
    return u;
}
__device__ __forceinline__ void mma8(float* c, const unsigned* a, const unsigned* b) {
    asm volatile(
        "mma.sync.aligned.m16n8k8.row.col.f32.tf32.tf32.f32 "
        "{%0,%1,%2,%3},{%4,%5,%6,%7},{%8,%9},{%0,%1,%2,%3};"
        : "+f"(c[0]), "+f"(c[1]), "+f"(c[2]), "+f"(c[3])
        : "r"(a[0]), "r"(a[1]), "r"(a[2]), "r"(a[3]), "r"(b[0]), "r"(b[1]));
}
__device__ __forceinline__ void ldsm4(unsigned& r0, unsigned& r1, unsigned& r2, unsigned& r3,
                                      const void* p) {
    unsigned a = (unsigned)__cvta_generic_to_shared(p);
    asm volatile("ldmatrix.sync.aligned.m8n8.x4.shared.b16 {%0,%1,%2,%3},[%4];"
                 : "=r"(r0), "=r"(r1), "=r"(r2), "=r"(r3) : "r"(a));
}
__device__ __forceinline__ uint4 cvt4(float4 v) {
    uint4 u;
    u.x = f2tf(v.x); u.y = f2tf(v.y); u.z = f2tf(v.z); u.w = f2tf(v.w);
    return u;
}
__device__ __forceinline__ void red2(float* p, float v0, float v1) {
    asm volatile("red.global.add.v2.f32 [%0], {%1,%2};" :: "l"(p), "f"(v0), "f"(v1) : "memory");
}

// ---------------- K0: routing logits GEMM (fp32 FFMA), split-K x4 ----------------
__global__ __launch_bounds__(256) void k_logits(const float* __restrict__ x,
                                                const float* __restrict__ gw) {
    const int m0 = blockIdx.x * 64;
    const int ks = blockIdx.y;
    __shared__ float As[64][17];
    __shared__ float Bs[64][17];
    const int tid = threadIdx.x;
    const int tr = tid >> 4, tc = tid & 15;
    float acc[4][4] = {};
    const int r = tid >> 2, s4 = (tid & 3) * 4;
    const int kbeg = ks * (H / KSPLIT), kend = kbeg + H / KSPLIT;
    for (int k0 = kbeg; k0 < kend; k0 += 16) {
        float4 av = *(const float4*)(x + (size_t)(m0 + r) * H + k0 + s4);
        float4 bv = *(const float4*)(gw + (size_t)r * H + k0 + s4);
        __syncthreads();
        As[r][s4+0]=av.x; As[r][s4+1]=av.y; As[r][s4+2]=av.z; As[r][s4+3]=av.w;
        Bs[r][s4+0]=bv.x; Bs[r][s4+1]=bv.y; Bs[r][s4+2]=bv.z; Bs[r][s4+3]=bv.w;
        __syncthreads();
#pragma unroll
        for (int kk = 0; kk < 16; kk++) {
            float a[4], b[4];
#pragma unroll
            for (int i = 0; i < 4; i++) { a[i] = As[tr*4+i][kk]; b[i] = Bs[tc*4+i][kk]; }
#pragma unroll
            for (int i = 0; i < 4; i++)
#pragma unroll
                for (int j = 0; j < 4; j++) acc[i][j] += a[i] * b[j];
        }
    }
#pragma unroll
    for (int i = 0; i < 4; i++)
#pragma unroll
        for (int j = 0; j < 4; j++)
            d_logits4[ks][(size_t)(m0 + tr*4 + i) * E + tc*4 + j] = acc[i][j];
}

// ---------------- K1: top-8 (warp argmax) + softmax + shared-gate sigmoid ----------
__global__ __launch_bounds__(64) void k_topk(const float* __restrict__ x,
                                             const float* __restrict__ sh1) {
    const int n = blockIdx.x;
    const int t = threadIdx.x;
    const int lane = t & 31, w = t >> 5;
    __shared__ float red[2];
    float p = 0.f;
    const float* xr = x + (size_t)n * H;
    for (int i = t; i < H; i += 64) p += xr[i] * sh1[i];
#pragma unroll
    for (int off = 16; off; off >>= 1) p += __shfl_xor_sync(0xffffffffu, p, off);
    if (lane == 0) red[w] = p;
    __syncthreads();
    if (t == 0) {
        float s = red[0] + red[1];
        d_shg[n] = 1.f / (1.f + expf(-s));
    }
    if (w == 0) {
        float a = 0.f, b = 0.f;
#pragma unroll
        for (int ps = 0; ps < KSPLIT; ps++) {
            a += d_logits4[ps][(size_t)n * E + lane];
            b += d_logits4[ps][(size_t)n * E + 32 + lane];
        }
        float vv[TOPK]; int ii[TOPK];
#pragma unroll
        for (int k = 0; k < TOPK; k++) {
            float m; int mi;
            if (a >= b) { m = a; mi = lane; } else { m = b; mi = lane + 32; }
#pragma unroll
            for (int off = 16; off; off >>= 1) {
                float om = __shfl_xor_sync(0xffffffffu, m, off);
                int   oi = __shfl_xor_sync(0xffffffffu, mi, off);
                if (om > m || (om == m && oi < mi)) { m = om; mi = oi; }
            }
            vv[k] = m; ii[k] = mi;
            if (lane == (mi & 31)) { if (mi < 32) a = -INFINITY; else b = -INFINITY; }
        }
        if (lane == 0) {
            float mx = vv[0], se = 0.f, ev[TOPK];
#pragma unroll
            for (int k = 0; k < TOPK; k++) { ev[k] = expf(vv[k] - mx); se += ev[k]; }
#pragma unroll
            for (int k = 0; k < TOPK; k++) {
                d_topi[n * TOPK + k] = ii[k];
                d_topw[n * TOPK + k] = ev[k] / se;
            }
        }
    }
}

// ---------------- K2: deterministic per-expert compaction ----------------
__global__ __launch_bounds__(256) void k_build() {
    const int e = blockIdx.x, t = threadIdx.x;
    __shared__ int wsum[8];
    __shared__ int base_s;
    if (t == 0) base_s = 0;
    __syncthreads();
    for (int c0 = 0; c0 < N_TOK * TOPK; c0 += 256) {
        int idx = c0 + t;
        int pred = (d_topi[idx] == e) ? 1 : 0;
        unsigned bal = __ballot_sync(0xffffffffu, pred);
        if ((t & 31) == 0) wsum[t >> 5] = __popc(bal);
        __syncthreads();
        int off = 0;
#pragma unroll
        for (int w = 0; w < 8; w++) if (w < (t >> 5)) off += wsum[w];
        int tot = 0;
#pragma unroll
        for (int w = 0; w < 8; w++) tot += wsum[w];
        int pos = base_s + off + __popc(bal & ((1u << (t & 31)) - 1u));
        if (pred && pos < CAP) {
            d_lists[e * CAP + pos] = idx >> 3;
            d_lw[e * CAP + pos] = d_topw[idx];
        }
        __syncthreads();
        if (t == 0) base_s += tot;
        __syncthreads();
    }
    if (t == 0) d_counts[e] = (base_s > CAP) ? CAP : base_s;
}

// ---------------- K3: fused gate/up tf32 GEMM, 64x64 warp tiles ----------------
// grid (E+1, 8, 8), 128 threads. bx<E: expert (y tiles 0..1 active); bx==E: shared.
__global__ __launch_bounds__(128) void k_gated(const float* __restrict__ x,
                                               const float* __restrict__ gu_w,
                                               const float* __restrict__ shg_w,
                                               const float* __restrict__ shu_w) {
    const int e = blockIdx.x;
    const bool moe = (e < E);
    const int m0 = blockIdx.y * 128;
    const int j0 = blockIdx.z * 64;
    const int cnt = moe ? d_counts[e] : N_TOK;
    if (m0 >= cnt) return;
    const float* Bg = moe ? gu_w + ((size_t)e * 2 * I_DIM + j0) * H : shg_w + (size_t)j0 * H;
    const float* Bu = moe ? gu_w + ((size_t)e * 2 * I_DIM + I_DIM + j0) * H : shu_w + (size_t)j0 * H;

    __shared__ __align__(16) float As[2][128][KC + 4];
    __shared__ __align__(16) float Bs[2][128][KC + 4];   // rows 0-63 gate, 64-127 up
    __shared__ int toks[128];
    __shared__ float wr[128];

    const int tid = threadIdx.x;
    {
        int slot = m0 + tid;
        if (moe) {
            bool v = slot < cnt;
            toks[tid] = v ? d_lists[e * CAP + slot] : 0;
            wr[tid]   = v ? d_lw[e * CAP + slot] : 0.f;
        } else { toks[tid] = slot; wr[tid] = 1.f; }
    }
    __syncthreads();

    // staging: 4 A chunks + 4 B chunks of 16B per thread per stage
    const float* aptr[4];
    const float* bptr[4];
    int ar[4], aseg[4], brr[4], bseg[4];
#pragma unroll
    for (int i = 0; i < 4; i++) {
        int c = tid + i * 128;
        ar[i] = c >> 2; aseg[i] = c & 3;
        aptr[i] = x + (size_t)toks[ar[i]] * H + aseg[i] * 4;
        brr[i] = c >> 2; bseg[i] = c & 3;
        bptr[i] = ((brr[i] < 64) ? Bg + (size_t)brr[i] * H
                                 : Bu + (size_t)(brr[i] - 64) * H) + bseg[i] * 4;
    }

    float4 pa[4], pb[4];
    auto ldg_stage = [&](int s) {
        int k0 = s * KC;
#pragma unroll
        for (int i = 0; i < 4; i++) pa[i] = *(const float4*)(aptr[i] + k0);
#pragma unroll
        for (int i = 0; i < 4; i++) pb[i] = *(const float4*)(bptr[i] + k0);
    };
    auto sts_stage = [&](int buf) {
#pragma unroll
        for (int i = 0; i < 4; i++)
            *(uint4*)&As[buf][ar[i]][aseg[i] * 4] = cvt4(pa[i]);
#pragma unroll
        for (int i = 0; i < 4; i++)
            *(uint4*)&Bs[buf][brr[i]][bseg[i] * 4] = cvt4(pb[i]);
    };

    float accG[4][4][4] = {}, accU[4][4][4] = {};
    const int warp = tid >> 5, lane = tid & 31;
    const int wm = warp & 1, wn = warp >> 1;
    const int g = lane >> 2, tg = lane & 3;
    const int lrow = lane & 15;
    const int ksh  = (lane >> 2) & 4;
    const int arow = wm * 64 + lrow;
    const int grow = wn * 32 + lrow;        // gate rows
    const int urow = 64 + wn * 32 + lrow;   // up rows
    const int NS = H / KC;   // 128

    ldg_stage(0);
    sts_stage(0);
    ldg_stage(1);
    __syncthreads();
    for (int s = 0; s < NS; s++) {
        const int buf = s & 1;
        if (s + 1 < NS) sts_stage(1 - buf);
        if (s + 2 < NS) ldg_stage(s + 2);
#pragma unroll
        for (int k8 = 0; k8 < KC / 8; k8++) {
            const int kc = k8 * 8 + ksh;
            unsigned Am[4][4];
#pragma unroll
            for (int mi = 0; mi < 4; mi++)
                ldsm4(Am[mi][0], Am[mi][1], Am[mi][2], Am[mi][3], &As[buf][arow + mi * 16][kc]);
            unsigned Gf[4][2], Uf[4][2];
            ldsm4(Gf[0][0], Gf[1][0], Gf[0][1], Gf[1][1], &Bs[buf][grow][kc]);
            ldsm4(Gf[2][0], Gf[3][0], Gf[2][1], Gf[3][1], &Bs[buf][grow + 16][kc]);
            ldsm4(Uf[0][0], Uf[1][0], Uf[0][1], Uf[1][1], &Bs[buf][urow][kc]);
            ldsm4(Uf[2][0], Uf[3][0], Uf[2][1], Uf[3][1], &Bs[buf][urow + 16][kc]);
#pragma unroll
            for (int mi = 0; mi < 4; mi++)
#pragma unroll
                for (int ni = 0; ni < 4; ni++) {
                    mma8(accG[mi][ni], Am[mi], Gf[ni]);
                    mma8(accU[mi][ni], Am[mi], Uf[ni]);
                }
        }
        __syncthreads();
    }

    // epilogue: inter = tf32( silu(gate)*up*route_w )
#pragma unroll
    for (int mi = 0; mi < 4; mi++)
#pragma unroll
        for (int ni = 0; ni < 4; ni++) {
#pragma unroll
            for (int hh = 0; hh < 2; hh++) {
                int r = wm * 64 + mi * 16 + g + hh * 8;
                int slot = m0 + r;
                if (slot < cnt) {
                    float w = wr[r];
                    int col = j0 + wn * 32 + ni * 8 + 2 * tg;
                    float g0 = accG[mi][ni][hh*2+0], g1 = accG[mi][ni][hh*2+1];
                    float u0 = accU[mi][ni][hh*2+0], u1 = accU[mi][ni][hh*2+1];
                    float v0 = (g0 / (1.f + __expf(-g0))) * u0 * w;
                    float v1 = (g1 / (1.f + __expf(-g1))) * u1 * w;
                    float* dst = moe ? d_inter + ((size_t)e * CAP + slot) * I_DIM
                                     : d_intersh + (size_t)slot * I_DIM;
                    dst[col]     = __uint_as_float(f2tf(v0));
                    dst[col + 1] = __uint_as_float(f2tf(v1));
                }
            }
        }
}

// ---------------- K4: down-projection tf32 GEMM, 64x64 warp tiles -------------
// A (d_inter/d_intersh) is already tf32 bits: no cvt on A path.
template <bool MOE>
__global__ __launch_bounds__(128) void k_down(const float* __restrict__ Bsrc,
                                              float* __restrict__ out) {
    const int e = MOE ? blockIdx.x : 0;
    const int m0 = blockIdx.y * 128, h0 = blockIdx.z * 128;
    const int cnt = MOE ? d_counts[e] : N_TOK;
    if (m0 >= cnt) return;
    const float* A = MOE ? d_inter + (size_t)e * CAP * I_DIM : d_intersh;
    const float* B = MOE ? Bsrc + ((size_t)e * H + h0) * I_DIM : Bsrc + (size_t)h0 * I_DIM;

    __shared__ __align__(16) float As[2][128][KC + 4];
    __shared__ __align__(16) float Bs2[2][128][KC + 4];
    __shared__ int toks[128];
    __shared__ float scl[128];

    const int tid = threadIdx.x;
    {
        int slot = m0 + tid;
        if (MOE) toks[tid] = (slot < cnt) ? d_lists[e * CAP + slot] : 0;
        else     scl[tid] = d_shg[slot];
    }
    __syncthreads();

    const float* aptr[4];
    const float* bptr[4];
    int ar[4], aseg[4], brr[4], bseg[4];
#pragma unroll
    for (int i = 0; i < 4; i++) {
        int c = tid + i * 128;
        ar[i] = c >> 2; aseg[i] = c & 3;
        aptr[i] = A + (size_t)(m0 + ar[i]) * I_DIM + aseg[i] * 4;
        brr[i] = c >> 2; bseg[i] = c & 3;
        bptr[i] = B + (size_t)brr[i] * I_DIM + bseg[i] * 4;
    }

    float4 pa[4], pb[4];
    auto ldg_stage = [&](int s) {
        int k0 = s * KC;
#pragma unroll
        for (int i = 0; i < 4; i++) pa[i] = *(const float4*)(aptr[i] + k0);
#pragma unroll
        for (int i = 0; i < 4; i++) pb[i] = *(const float4*)(bptr[i] + k0);
    };
    auto sts_stage = [&](int buf) {
#pragma unroll
        for (int i = 0; i < 4; i++)
            *(float4*)&As[buf][ar[i]][aseg[i] * 4] = pa[i];      // already tf32 bits
#pragma unroll
        for (int i = 0; i < 4; i++)
            *(uint4*)&Bs2[buf][brr[i]][bseg[i] * 4] = cvt4(pb[i]);
    };

    float acc[4][8][4] = {};
    const int warp = tid >> 5, lane = tid & 31;
    const int wm = warp & 1, wn = warp >> 1;
    const int g = lane >> 2, tg = lane & 3;
    const int lrow = lane & 15;
    const int ksh  = (lane >> 2) & 4;
    const int arow = wm * 64 + lrow;
    const int brow = wn * 64 + lrow;
    const int NS = I_DIM / KC;   // 32

    ldg_stage(0);
    sts_stage(0);
    ldg_stage(1);
    __syncthreads();
    for (int s = 0; s < NS; s++) {
        const int buf = s & 1;
        if (s + 1 < NS) sts_stage(1 - buf);
        if (s + 2 < NS) ldg_stage(s + 2);
#pragma unroll
        for (int k8 = 0; k8 < KC / 8; k8++) {
            const int kc = k8 * 8 + ksh;
            unsigned Am[4][4];
#pragma unroll
            for (int mi = 0; mi < 4; mi++)
                ldsm4(Am[mi][0], Am[mi][1], Am[mi][2], Am[mi][3], &As[buf][arow + mi * 16][kc]);
            unsigned Bf[8][2];
#pragma unroll
            for (int nq = 0; nq < 4; nq++)
                ldsm4(Bf[nq*2][0], Bf[nq*2+1][0], Bf[nq*2][1], Bf[nq*2+1][1],
                      &Bs2[buf][brow + nq * 16][kc]);
#pragma unroll
            for (int mi = 0; mi < 4; mi++)
#pragma unroll
                for (int ni = 0; ni < 8; ni++)
                    mma8(acc[mi][ni], Am[mi], Bf[ni]);
        }
        __syncthreads();
    }

#pragma unroll
    for (int mi = 0; mi < 4; mi++)
#pragma unroll
        for (int ni = 0; ni < 8; ni++) {
#pragma unroll
            for (int hh = 0; hh < 2; hh++) {
                int r = wm * 64 + mi * 16 + g + hh * 8;
                int slot = m0 + r;
                int col = h0 + wn * 64 + ni * 8 + 2 * tg;
                float v0 = acc[mi][ni][hh*2+0];
                float v1 = acc[mi][ni][hh*2+1];
                if (MOE) {
                    if (slot < cnt) {
                        int tk = toks[r];
                        red2(out + (size_t)tk * H + col, v0, v1);
                    }
                } else {
                    float sc = scl[r];
                    out[(size_t)slot * H + col]     = sc * v0;
                    out[(size_t)slot * H + col + 1] = sc * v1;
                }
            }
        }
}

// ---------------- launcher ----------------
extern "C" void kernel_launch(void* const* d_in, const int* in_sizes, int n_in,
                              void* d_out, int out_size) {
    (void)in_sizes; (void)n_in; (void)out_size;
    const float* x      = (const float*)d_in[0];
    const float* gate_w = (const float*)d_in[1];
    const float* gu_w   = (const float*)d_in[2];
    const float* dp_w   = (const float*)d_in[3];
    const float* shg_w  = (const float*)d_in[4];
    const float* shu_w  = (const float*)d_in[5];
    const float* shd_w  = (const float*)d_in[6];
    const float* sh1    = (const float*)d_in[7];
    float* out = (float*)d_out;

    k_logits<<<dim3(16, KSPLIT), 256>>>(x, gate_w);
    k_topk<<<N_TOK, 64>>>(x, sh1);
    k_build<<<E, 256>>>();
    k_gated<<<dim3(E + 1, 8, 8), 128>>>(x, gu_w, shg_w, shu_w);  // experts + shared fused
    k_down<false><<<dim3(1, 8, 16), 128>>>(shd_w, out);          // init out: FULL H coverage
    k_down<true><<<dim3(E, 2, 16), 128>>>(dp_w, out);            // red.v2-accumulate experts
}